// round 6
// baseline (speedup 1.0000x reference)
#include <cuda_runtime.h>
#include <cstdint>

#define N_PTS    4096
#define N_QUERY  35328     // 64*552
#define NSAMPLE  32
#define FEAT_D   32
#define FEAT_H   64
#define OUT_BASE 384       // 64*6 src_keypts floats precede grouped output
#define ROW      35        // 3+FEAT_D
#define QROW     1120      // NSAMPLE*ROW
#define NBUCKET  256
#define CAND_CAP 64

// -------- scratch (static device globals: allocation-free) --------
__device__ float4 g_xyzp[N_PTS];             // tgt xyz + |p|^2
__device__ float  g_feat[N_PTS * FEAT_D];    // tgt feature rows [n][32]
__device__ float  g_scores[N_PTS];           // src softplus scores

// monotone float -> uint mapping (total order incl. negatives)
__device__ __forceinline__ unsigned int fmap(float f) {
    unsigned int u = __float_as_uint(f);
    return (u & 0x80000000u) ? ~u : (u | 0x80000000u);
}
__device__ __forceinline__ unsigned long long umin64(unsigned long long a, unsigned long long b) {
    return a < b ? a : b;
}
__device__ __forceinline__ unsigned long long umax64(unsigned long long a, unsigned long long b) {
    return a > b ? a : b;
}
__device__ __forceinline__ unsigned long long shfl_xor64(unsigned long long v, int m) {
    return __shfl_xor_sync(0xffffffffu, v, m);
}

// ---------------------------------------------------------------
// Kernel 1: feature MLP (fused src+tgt via blockIdx.y).
//   y==0: tgt (write g_xyzp + g_feat);  y==1: src (write g_scores)
// fp32 op order mirrors the XLA reference (fma-chain contractions).
// Incremental accumulation over k keeps regs low (no h[64] array);
// the k-chain order is identical to the reference.
// ---------------------------------------------------------------
__global__ void __launch_bounds__(128) feat_kernel(
    const float* __restrict__ tgt_pts,
    const float* __restrict__ src_pts,
    const float* __restrict__ W1, const float* __restrict__ b1,
    const float* __restrict__ W2, const float* __restrict__ b2,
    const float* __restrict__ Wq, const float* __restrict__ bq)
{
    __shared__ float sW1[FEAT_H * 6], sb1[FEAT_H];
    __shared__ float sW2t[FEAT_H * FEAT_D];   // transposed: [k][o2]
    __shared__ float sb2[FEAT_D];
    __shared__ float sWq[FEAT_D], sbq;

    int tid  = threadIdx.x;
    int mode = blockIdx.y;           // 0 = tgt, 1 = src
    const float* pts = mode ? src_pts : tgt_pts;

    for (int i = tid; i < FEAT_H * 6; i += 128) sW1[i] = W1[i];
    for (int i = tid; i < FEAT_H;     i += 128) sb1[i] = b1[i];
    for (int i = tid; i < FEAT_D * FEAT_H; i += 128) {
        int o2 = i >> 6, k = i & 63;
        sW2t[k * FEAT_D + o2] = W2[i];
    }
    for (int i = tid; i < FEAT_D; i += 128) sb2[i] = b2[i];
    for (int i = tid; i < FEAT_D; i += 128) sWq[i] = Wq[i];
    if (tid == 0) sbq = bq[0];
    __syncthreads();

    int n = blockIdx.x * 128 + tid;

    float x[6];
#pragma unroll
    for (int c = 0; c < 6; c++) x[c] = pts[c * N_PTS + n];

    float facc[FEAT_D];
#pragma unroll 4
    for (int k = 0; k < FEAT_H; k++) {
        float acc = __fmul_rn(sW1[k * 6], x[0]);
#pragma unroll
        for (int c = 1; c < 6; c++) acc = __fmaf_rn(sW1[k * 6 + c], x[c], acc);
        float h = fmaxf(__fadd_rn(acc, sb1[k]), 0.0f);
        const float* w = &sW2t[k * FEAT_D];
        if (k == 0) {
#pragma unroll
            for (int o = 0; o < FEAT_D; o++) facc[o] = __fmul_rn(w[o], h);
        } else {
#pragma unroll
            for (int o = 0; o < FEAT_D; o++) facc[o] = __fmaf_rn(w[o], h, facc[o]);
        }
    }

    if (mode == 0) {
#pragma unroll
        for (int o = 0; o < FEAT_D; o++)
            g_feat[n * FEAT_D + o] = fmaxf(__fadd_rn(facc[o], sb2[o]), 0.0f);
        float pp = __fadd_rn(__fadd_rn(__fmul_rn(x[0], x[0]), __fmul_rn(x[1], x[1])),
                             __fmul_rn(x[2], x[2]));
        g_xyzp[n] = make_float4(x[0], x[1], x[2], pp);
    } else {
        float z = 0.0f;
#pragma unroll
        for (int o = 0; o < FEAT_D; o++) {
            float f = fmaxf(__fadd_rn(facc[o], sb2[o]), 0.0f);
            z = (o == 0) ? __fmul_rn(sWq[0], f) : __fmaf_rn(sWq[o], f, z);
        }
        z = __fadd_rn(z, sbq);
        // jax.nn.softplus = max(z,0) + log1p(exp(-|z|))
        g_scores[n] = __fadd_rn(fmaxf(z, 0.0f), log1pf(expf(-fabsf(z))));
    }
}

// ---------------------------------------------------------------
// Kernel 2: src top-64 (descending score, tie -> lower index) via
// chunk-max cache + warp tournament; then gather src_keypts [64,6].
// ---------------------------------------------------------------
__global__ void __launch_bounds__(128) topk_src_kernel(
    const float* __restrict__ src_pts, float* __restrict__ out)
{
    __shared__ float ss[N_PTS];                  // 16 KB
    __shared__ unsigned long long schunk[128];
    __shared__ int ssel[64];

    int tid = threadIdx.x;
    for (int i = tid; i < N_PTS; i += 128) ss[i] = g_scores[i];
    __syncthreads();

    {
        int c = tid;
        unsigned long long best = 0ull;
        for (int j = 0; j < 32; j++) {
            int i = (c << 5) + ((j + c) & 31);
            unsigned long long key = ((unsigned long long)fmap(ss[i]) << 32) |
                                     (unsigned long long)(0xFFFFFFFFu - (unsigned)i);
            best = umax64(best, key);
        }
        schunk[c] = best;
    }
    __syncthreads();

    if (tid < 32) {
        for (int k = 0; k < 64; k++) {
            unsigned long long b = 0ull;
#pragma unroll
            for (int j = 0; j < 4; j++) b = umax64(b, schunk[tid + 32 * j]);
#pragma unroll
            for (int off = 16; off; off >>= 1)
                b = umax64(b, shfl_xor64(b, off));

            int w = (int)(0xFFFFFFFFu - (unsigned)(b & 0xFFFFFFFFull));
            int cidx = w >> 5;
            if (tid == 0) ss[w] = __int_as_float(0xFF800000); // -inf: removed
            __syncwarp();
            int i2 = (cidx << 5) + tid;
            unsigned long long key2 = ((unsigned long long)fmap(ss[i2]) << 32) |
                                      (unsigned long long)(0xFFFFFFFFu - (unsigned)i2);
#pragma unroll
            for (int off = 16; off; off >>= 1)
                key2 = umax64(key2, shfl_xor64(key2, off));
            if (tid == 0) { schunk[cidx] = key2; ssel[k] = w; }
            __syncwarp();
        }
    }
    __syncthreads();

    for (int e = tid; e < 384; e += 128) {
        int kk = e / 6, c = e - kk * 6;
        out[e] = src_pts[c * N_PTS + ssel[kk]];
    }
}

// ---------------------------------------------------------------
// Kernel 3: ball query nearest-32 + gather. One block per query.
// Distances stay in registers (d[32] per thread). 256-bucket smem
// histogram locates the cut; candidates -> 64-wide warp bitonic
// sort on (fmap(d),idx). Exact fallback on candidate overflow.
// ---------------------------------------------------------------
__global__ void __launch_bounds__(128) ball_kernel(
    const float* __restrict__ cand,
    float* __restrict__ out)
{
    __shared__ unsigned int hist[NBUCKET];       // 1 KB
    __shared__ int swt[4];
    __shared__ unsigned long long scand[CAND_CAP];
    __shared__ unsigned long long sred[128];
    __shared__ int ssel[NSAMPLE];
    __shared__ int scut, scnt;

    const unsigned long long INVK = ~0ull;
    int tid  = threadIdx.x;
    int lane = tid & 31;
    int wid  = tid >> 5;
    int qid  = blockIdx.x;

    hist[tid] = 0; hist[tid + 128] = 0;
    if (tid == 0) { scut = NBUCKET - 1; scnt = 0; }

    float q0 = __ldg(&cand[qid * 3 + 0]);
    float q1 = __ldg(&cand[qid * 3 + 1]);
    float q2 = __ldg(&cand[qid * 3 + 2]);
    float qq = __fadd_rn(__fadd_rn(__fmul_rn(q0, q0), __fmul_rn(q1, q1)),
                         __fmul_rn(q2, q2));
    __syncthreads();

    // Pass 1: distances (reference formula: qq - 2*dot + pp), registers + hist
    float d[32];
#pragma unroll
    for (int j = 0; j < 32; j++) {
        int p = j * 128 + tid;
        float4 P = g_xyzp[p];
        float E = __fmaf_rn(P.z, q2, __fmaf_rn(P.y, q1, __fmul_rn(P.x, q0)));
        float dd = __fadd_rn(__fsub_rn(qq, __fmul_rn(2.0f, E)), P.w);
        d[j] = dd;
        if (dd <= 4.0f) {
            int b = (int)(dd * 64.0f);
            b = b < 0 ? 0 : (b > NBUCKET - 1 ? NBUCKET - 1 : b);
            atomicAdd(&hist[b], 1u);
        }
    }
    __syncthreads();

    // Locate cut bucket: thread t owns buckets {2t, 2t+1}
    {
        int h0 = hist[2 * tid], h1 = hist[2 * tid + 1];
        int psum = h0 + h1;
        int v = psum;
#pragma unroll
        for (int off = 1; off < 32; off <<= 1) {
            int u = __shfl_up_sync(0xffffffffu, v, off);
            if (lane >= off) v += u;
        }
        if (lane == 31) swt[wid] = v;
        __syncthreads();
        int woff = 0;
#pragma unroll
        for (int w = 0; w < 4; w++) if (w < wid) woff += swt[w];
        int total = swt[0] + swt[1] + swt[2] + swt[3];
        int incl = v + woff;
        int excl = incl - psum;
        if (total >= NSAMPLE && excl < NSAMPLE && incl >= NSAMPLE) {
            scut = (excl + h0 >= NSAMPLE) ? 2 * tid : 2 * tid + 1;
        }
    }
    __syncthreads();
    int cut = scut;

    // Pass 2: collect candidates with bucket <= cut (registers, no reload)
#pragma unroll
    for (int j = 0; j < 32; j++) {
        float dd = d[j];
        if (dd <= 4.0f) {
            int b = (int)(dd * 64.0f);
            b = b < 0 ? 0 : (b > NBUCKET - 1 ? NBUCKET - 1 : b);
            if (b <= cut) {
                int pos = atomicAdd(&scnt, 1);
                if (pos < CAND_CAP)
                    scand[pos] = ((unsigned long long)fmap(dd) << 32) |
                                 (unsigned long long)(unsigned)(j * 128 + tid);
            }
        }
    }
    __syncthreads();
    int cnt = scnt;

    if (cnt <= CAND_CAP) {
        // warp 0: 64-element bitonic sort (2 keys per lane), ascending
        if (tid < 32) {
            unsigned long long a = (tid      < cnt) ? scand[tid]      : INVK;
            unsigned long long b = (tid + 32 < cnt) ? scand[tid + 32] : INVK;
            for (int k = 2; k <= 64; k <<= 1) {
                for (int j = k >> 1; j > 0; j >>= 1) {
                    if (j == 32) {
                        unsigned long long lo = umin64(a, b), hi = umax64(a, b);
                        a = lo; b = hi;
                    } else {
                        {
                            unsigned long long o = shfl_xor64(a, j);
                            bool asc = ((tid & k) == 0);
                            bool keepmin = (((tid & j) == 0) == asc);
                            a = keepmin ? umin64(a, o) : umax64(a, o);
                        }
                        {
                            unsigned long long o = shfl_xor64(b, j);
                            bool asc = (((tid + 32) & k) == 0);
                            bool keepmin = (((tid & j) == 0) == asc);
                            b = keepmin ? umin64(b, o) : umax64(b, o);
                        }
                    }
                }
            }
            unsigned long long a0 = __shfl_sync(0xffffffffu, a, 0);
            int myidx = (int)(unsigned)(a & 0xFFFFFFFFull);
            int idx0  = (int)(unsigned)(a0 & 0xFFFFFFFFull);
            bool av = (a != INVK), v0 = (a0 != INVK);
            ssel[tid] = av ? myidx : (v0 ? idx0 : 0);
        }
    } else {
        // exact fallback (degenerate tie explosion): 32 block-wide argmins
        unsigned int removed = 0u;
        for (int k = 0; k < NSAMPLE; k++) {
            unsigned long long best = INVK;
#pragma unroll
            for (int j = 0; j < 32; j++) {
                if (!((removed >> j) & 1u) && d[j] <= 4.0f)
                    best = umin64(best, ((unsigned long long)fmap(d[j]) << 32) |
                                        (unsigned long long)(unsigned)(j * 128 + tid));
            }
            sred[tid] = best;
            __syncthreads();
            for (int st = 64; st; st >>= 1) {
                if (tid < st) sred[tid] = umin64(sred[tid], sred[tid + st]);
                __syncthreads();
            }
            unsigned long long bb = sred[0];
            int w = (bb != INVK) ? (int)(unsigned)(bb & 0xFFFFFFFFull)
                                 : (k ? ssel[0] : 0);
            if ((w & 127) == tid && bb != INVK) removed |= 1u << (w >> 7);
            if (tid == 0) ssel[k] = w;
            __syncthreads();
        }
    }
    __syncthreads();

    // Output: [NSAMPLE][3+FEAT_D] per query, vectorized float4 stores
    float4* ob = (float4*)(out + OUT_BASE + (long long)qid * QROW);
    for (int v = tid; v < QROW / 4; v += 128) {
        int e = v * 4;
        int s = e / ROW;
        int c = e - s * ROW;
        float r[4];
#pragma unroll
        for (int t = 0; t < 4; t++) {
            int idx = ssel[s];
            float val;
            if (c < 3) {
                const float* Pf = (const float*)&g_xyzp[idx];
                float qc = (c == 0) ? q0 : ((c == 1) ? q1 : q2);
                val = __fsub_rn(Pf[c], qc);
            } else {
                val = g_feat[idx * FEAT_D + (c - 3)];
            }
            r[t] = val;
            if (++c == ROW) { c = 0; ++s; }
        }
        ob[v] = make_float4(r[0], r[1], r[2], r[3]);
    }
}

// ---------------------------------------------------------------
extern "C" void kernel_launch(void* const* d_in, const int* in_sizes, int n_in,
                              void* d_out, int out_size)
{
    const float* src_pts = (const float*)d_in[0];
    const float* tgt_pts = (const float*)d_in[1];
    const float* cand    = (const float*)d_in[2];
    const float* W1      = (const float*)d_in[3];
    const float* b1      = (const float*)d_in[4];
    const float* W2      = (const float*)d_in[5];
    const float* b2      = (const float*)d_in[6];
    const float* Wq      = (const float*)d_in[7];
    const float* bq      = (const float*)d_in[8];
    float* out = (float*)d_out;

    feat_kernel<<<dim3(N_PTS / 128, 2), 128>>>(tgt_pts, src_pts, W1, b1, W2, b2, Wq, bq);
    topk_src_kernel<<<1, 128>>>(src_pts, out);
    ball_kernel<<<N_QUERY, 128>>>(cand, out);
}

// round 7
// speedup vs baseline: 1.5977x; 1.5977x over previous
#include <cuda_runtime.h>
#include <cstdint>

#define N_PTS    4096
#define N_QUERY  35328     // 64*552
#define NSAMPLE  32
#define FEAT_D   32
#define FEAT_H   64
#define OUT_BASE 384       // 64*6 src_keypts floats precede grouped output
#define ROW      35        // 3+FEAT_D
#define QROW     1120      // NSAMPLE*ROW
#define NBUCKET  256
#define CAND_CAP 64

// -------- scratch (static device globals: allocation-free) --------
__device__ float4 g_xyzp[N_PTS];             // tgt xyz + |p|^2
__device__ float  g_feat[N_PTS * FEAT_D];    // tgt feature rows [n][32]
__device__ float  g_scores[N_PTS];           // src softplus scores

// monotone float -> uint mapping (total order incl. negatives)
__device__ __forceinline__ unsigned int fmap(float f) {
    unsigned int u = __float_as_uint(f);
    return (u & 0x80000000u) ? ~u : (u | 0x80000000u);
}
__device__ __forceinline__ unsigned long long umin64(unsigned long long a, unsigned long long b) {
    return a < b ? a : b;
}
__device__ __forceinline__ unsigned long long umax64(unsigned long long a, unsigned long long b) {
    return a > b ? a : b;
}
__device__ __forceinline__ unsigned long long shfl_xor64(unsigned long long v, int m) {
    return __shfl_xor_sync(0xffffffffu, v, m);
}

// ---------------------------------------------------------------
// Kernel 1: feature MLP (fused src+tgt via blockIdx.y).
//   y==0: tgt (write g_xyzp + g_feat);  y==1: src (write g_scores)
// fp32 op order mirrors the XLA reference (fma-chain contractions).
// ---------------------------------------------------------------
__global__ void __launch_bounds__(128) feat_kernel(
    const float* __restrict__ tgt_pts,
    const float* __restrict__ src_pts,
    const float* __restrict__ W1, const float* __restrict__ b1,
    const float* __restrict__ W2, const float* __restrict__ b2,
    const float* __restrict__ Wq, const float* __restrict__ bq)
{
    __shared__ float sW1[FEAT_H * 6], sb1[FEAT_H];
    __shared__ float sW2t[FEAT_H * FEAT_D];   // transposed: [k][o2]
    __shared__ float sb2[FEAT_D];
    __shared__ float sWq[FEAT_D], sbq;

    int tid  = threadIdx.x;
    int mode = blockIdx.y;           // 0 = tgt, 1 = src
    const float* pts = mode ? src_pts : tgt_pts;

    for (int i = tid; i < FEAT_H * 6; i += 128) sW1[i] = W1[i];
    for (int i = tid; i < FEAT_H;     i += 128) sb1[i] = b1[i];
    for (int i = tid; i < FEAT_D * FEAT_H; i += 128) {
        int o2 = i >> 6, k = i & 63;
        sW2t[k * FEAT_D + o2] = W2[i];
    }
    for (int i = tid; i < FEAT_D; i += 128) sb2[i] = b2[i];
    for (int i = tid; i < FEAT_D; i += 128) sWq[i] = Wq[i];
    if (tid == 0) sbq = bq[0];
    __syncthreads();

    int n = blockIdx.x * 128 + tid;

    float x[6];
#pragma unroll
    for (int c = 0; c < 6; c++) x[c] = pts[c * N_PTS + n];

    float facc[FEAT_D];
#pragma unroll 4
    for (int k = 0; k < FEAT_H; k++) {
        float acc = __fmul_rn(sW1[k * 6], x[0]);
#pragma unroll
        for (int c = 1; c < 6; c++) acc = __fmaf_rn(sW1[k * 6 + c], x[c], acc);
        float h = fmaxf(__fadd_rn(acc, sb1[k]), 0.0f);
        const float* w = &sW2t[k * FEAT_D];
        if (k == 0) {
#pragma unroll
            for (int o = 0; o < FEAT_D; o++) facc[o] = __fmul_rn(w[o], h);
        } else {
#pragma unroll
            for (int o = 0; o < FEAT_D; o++) facc[o] = __fmaf_rn(w[o], h, facc[o]);
        }
    }

    if (mode == 0) {
#pragma unroll
        for (int o = 0; o < FEAT_D; o++)
            g_feat[n * FEAT_D + o] = fmaxf(__fadd_rn(facc[o], sb2[o]), 0.0f);
        float pp = __fadd_rn(__fadd_rn(__fmul_rn(x[0], x[0]), __fmul_rn(x[1], x[1])),
                             __fmul_rn(x[2], x[2]));
        g_xyzp[n] = make_float4(x[0], x[1], x[2], pp);
    } else {
        float z = 0.0f;
#pragma unroll
        for (int o = 0; o < FEAT_D; o++) {
            float f = fmaxf(__fadd_rn(facc[o], sb2[o]), 0.0f);
            z = (o == 0) ? __fmul_rn(sWq[0], f) : __fmaf_rn(sWq[o], f, z);
        }
        z = __fadd_rn(z, sbq);
        // jax.nn.softplus = max(z,0) + log1p(exp(-|z|))
        g_scores[n] = __fadd_rn(fmaxf(z, 0.0f), log1pf(expf(-fabsf(z))));
    }
}

// ---------------------------------------------------------------
// Kernel 2: src top-64 (descending score, tie -> lower index) via
// chunk-max cache + warp tournament; then gather src_keypts [64,6].
// ---------------------------------------------------------------
__global__ void __launch_bounds__(128) topk_src_kernel(
    const float* __restrict__ src_pts, float* __restrict__ out)
{
    __shared__ float ss[N_PTS];                  // 16 KB
    __shared__ unsigned long long schunk[128];
    __shared__ int ssel[64];

    int tid = threadIdx.x;
    for (int i = tid; i < N_PTS; i += 128) ss[i] = g_scores[i];
    __syncthreads();

    {
        int c = tid;
        unsigned long long best = 0ull;
        for (int j = 0; j < 32; j++) {
            int i = (c << 5) + ((j + c) & 31);
            unsigned long long key = ((unsigned long long)fmap(ss[i]) << 32) |
                                     (unsigned long long)(0xFFFFFFFFu - (unsigned)i);
            best = umax64(best, key);
        }
        schunk[c] = best;
    }
    __syncthreads();

    if (tid < 32) {
        for (int k = 0; k < 64; k++) {
            unsigned long long b = 0ull;
#pragma unroll
            for (int j = 0; j < 4; j++) b = umax64(b, schunk[tid + 32 * j]);
#pragma unroll
            for (int off = 16; off; off >>= 1)
                b = umax64(b, shfl_xor64(b, off));

            int w = (int)(0xFFFFFFFFu - (unsigned)(b & 0xFFFFFFFFull));
            int cidx = w >> 5;
            if (tid == 0) ss[w] = __int_as_float(0xFF800000); // -inf: removed
            __syncwarp();
            int i2 = (cidx << 5) + tid;
            unsigned long long key2 = ((unsigned long long)fmap(ss[i2]) << 32) |
                                      (unsigned long long)(0xFFFFFFFFu - (unsigned)i2);
#pragma unroll
            for (int off = 16; off; off >>= 1)
                key2 = umax64(key2, shfl_xor64(key2, off));
            if (tid == 0) { schunk[cidx] = key2; ssel[k] = w; }
            __syncwarp();
        }
    }
    __syncthreads();

    for (int e = tid; e < 384; e += 128) {
        int kk = e / 6, c = e - kk * 6;
        out[e] = src_pts[c * N_PTS + ssel[kk]];
    }
}

// ---------------------------------------------------------------
// Kernel 3: ball query nearest-32 + gather. One block per query.
// No distance storage: pass 2 recomputes (bit-identical fp32 ops,
// L1-hit loads). Per-warp 256-bucket histograms -> warp-shfl scan
// -> cut bucket -> candidate collect -> 64-wide warp bitonic sort
// on (fmap(d),idx). Tiny smem (~5.8KB) -> ~12 CTAs/SM overlap.
// ---------------------------------------------------------------
__global__ void __launch_bounds__(128) ball_kernel(
    const float* __restrict__ cand,
    float* __restrict__ out)
{
    __shared__ unsigned int hist[4][NBUCKET];    // 4 KB, one per warp
    __shared__ int swt[4];
    __shared__ unsigned long long scand[CAND_CAP];
    __shared__ unsigned long long sred[128];
    __shared__ int ssel[NSAMPLE];
    __shared__ int scut, scnt;

    const unsigned long long INVK = ~0ull;
    int tid  = threadIdx.x;
    int lane = tid & 31;
    int wid  = tid >> 5;
    int qid  = blockIdx.x;

    unsigned int* hflat = &hist[0][0];
#pragma unroll
    for (int i = 0; i < 8; i++) hflat[tid + i * 128] = 0u;
    if (tid == 0) { scut = NBUCKET - 1; scnt = 0; }

    float q0 = __ldg(&cand[qid * 3 + 0]);
    float q1 = __ldg(&cand[qid * 3 + 1]);
    float q2 = __ldg(&cand[qid * 3 + 2]);
    float qq = __fadd_rn(__fadd_rn(__fmul_rn(q0, q0), __fmul_rn(q1, q1)),
                         __fmul_rn(q2, q2));
    __syncthreads();

    // Pass 1: distances (reference formula: qq - 2*dot + pp) -> per-warp hist
#pragma unroll 4
    for (int j = 0; j < 32; j++) {
        int p = j * 128 + tid;
        float4 P = g_xyzp[p];
        float E = __fmaf_rn(P.z, q2, __fmaf_rn(P.y, q1, __fmul_rn(P.x, q0)));
        float dd = __fadd_rn(__fsub_rn(qq, __fmul_rn(2.0f, E)), P.w);
        if (dd <= 4.0f) {
            int b = (int)(dd * 64.0f);
            b = b < 0 ? 0 : (b > NBUCKET - 1 ? NBUCKET - 1 : b);
            atomicAdd(&hist[wid][b], 1u);
        }
    }
    __syncthreads();

    // Locate cut bucket: thread t owns buckets {2t, 2t+1} (sum of 4 warps)
    {
        int h0 = hist[0][2 * tid] + hist[1][2 * tid] +
                 hist[2][2 * tid] + hist[3][2 * tid];
        int h1 = hist[0][2 * tid + 1] + hist[1][2 * tid + 1] +
                 hist[2][2 * tid + 1] + hist[3][2 * tid + 1];
        int psum = h0 + h1;
        int v = psum;
#pragma unroll
        for (int off = 1; off < 32; off <<= 1) {
            int u = __shfl_up_sync(0xffffffffu, v, off);
            if (lane >= off) v += u;
        }
        if (lane == 31) swt[wid] = v;
        __syncthreads();
        int woff = 0;
#pragma unroll
        for (int w = 0; w < 4; w++) if (w < wid) woff += swt[w];
        int total = swt[0] + swt[1] + swt[2] + swt[3];
        int incl = v + woff;
        int excl = incl - psum;
        if (total >= NSAMPLE && excl < NSAMPLE && incl >= NSAMPLE) {
            scut = (excl + h0 >= NSAMPLE) ? 2 * tid : 2 * tid + 1;
        }
    }
    __syncthreads();
    int cut = scut;

    // Pass 2: recompute distances (bit-identical), collect bucket <= cut
#pragma unroll 4
    for (int j = 0; j < 32; j++) {
        int p = j * 128 + tid;
        float4 P = g_xyzp[p];
        float E = __fmaf_rn(P.z, q2, __fmaf_rn(P.y, q1, __fmul_rn(P.x, q0)));
        float dd = __fadd_rn(__fsub_rn(qq, __fmul_rn(2.0f, E)), P.w);
        if (dd <= 4.0f) {
            int b = (int)(dd * 64.0f);
            b = b < 0 ? 0 : (b > NBUCKET - 1 ? NBUCKET - 1 : b);
            if (b <= cut) {
                int pos = atomicAdd(&scnt, 1);
                if (pos < CAND_CAP)
                    scand[pos] = ((unsigned long long)fmap(dd) << 32) |
                                 (unsigned long long)(unsigned)p;
            }
        }
    }
    __syncthreads();
    int cnt = scnt;

    if (cnt <= CAND_CAP) {
        // warp 0: 64-element bitonic sort (2 keys per lane), ascending
        if (tid < 32) {
            unsigned long long a = (tid      < cnt) ? scand[tid]      : INVK;
            unsigned long long b = (tid + 32 < cnt) ? scand[tid + 32] : INVK;
            for (int k = 2; k <= 64; k <<= 1) {
                for (int j = k >> 1; j > 0; j >>= 1) {
                    if (j == 32) {
                        unsigned long long lo = umin64(a, b), hi = umax64(a, b);
                        a = lo; b = hi;
                    } else {
                        {
                            unsigned long long o = shfl_xor64(a, j);
                            bool asc = ((tid & k) == 0);
                            bool keepmin = (((tid & j) == 0) == asc);
                            a = keepmin ? umin64(a, o) : umax64(a, o);
                        }
                        {
                            unsigned long long o = shfl_xor64(b, j);
                            bool asc = (((tid + 32) & k) == 0);
                            bool keepmin = (((tid & j) == 0) == asc);
                            b = keepmin ? umin64(b, o) : umax64(b, o);
                        }
                    }
                }
            }
            unsigned long long a0 = __shfl_sync(0xffffffffu, a, 0);
            int myidx = (int)(unsigned)(a & 0xFFFFFFFFull);
            int idx0  = (int)(unsigned)(a0 & 0xFFFFFFFFull);
            bool av = (a != INVK), v0 = (a0 != INVK);
            ssel[tid] = av ? myidx : (v0 ? idx0 : 0);
        }
    } else {
        // exact fallback (degenerate tie explosion): 32 block-wide argmins,
        // distances recomputed per round; removed set tracked per thread.
        unsigned int removed = 0u;
        for (int k = 0; k < NSAMPLE; k++) {
            unsigned long long best = INVK;
            for (int j = 0; j < 32; j++) {
                int p = j * 128 + tid;
                float4 P = g_xyzp[p];
                float E = __fmaf_rn(P.z, q2, __fmaf_rn(P.y, q1, __fmul_rn(P.x, q0)));
                float dd = __fadd_rn(__fsub_rn(qq, __fmul_rn(2.0f, E)), P.w);
                if (!((removed >> j) & 1u) && dd <= 4.0f)
                    best = umin64(best, ((unsigned long long)fmap(dd) << 32) |
                                        (unsigned long long)(unsigned)p);
            }
            sred[tid] = best;
            __syncthreads();
            for (int st = 64; st; st >>= 1) {
                if (tid < st) sred[tid] = umin64(sred[tid], sred[tid + st]);
                __syncthreads();
            }
            unsigned long long bb = sred[0];
            int w = (bb != INVK) ? (int)(unsigned)(bb & 0xFFFFFFFFull)
                                 : (k ? ssel[0] : 0);
            if ((w & 127) == tid && bb != INVK) removed |= 1u << (w >> 7);
            if (tid == 0) ssel[k] = w;
            __syncthreads();
        }
    }
    __syncthreads();

    // Output: [NSAMPLE][3+FEAT_D] per query, vectorized float4 stores
    float4* ob = (float4*)(out + OUT_BASE + (long long)qid * QROW);
    for (int v = tid; v < QROW / 4; v += 128) {
        int e = v * 4;
        int s = e / ROW;
        int c = e - s * ROW;
        float r[4];
#pragma unroll
        for (int t = 0; t < 4; t++) {
            int idx = ssel[s];
            float val;
            if (c < 3) {
                const float* Pf = (const float*)&g_xyzp[idx];
                float qc = (c == 0) ? q0 : ((c == 1) ? q1 : q2);
                val = __fsub_rn(Pf[c], qc);
            } else {
                val = g_feat[idx * FEAT_D + (c - 3)];
            }
            r[t] = val;
            if (++c == ROW) { c = 0; ++s; }
        }
        ob[v] = make_float4(r[0], r[1], r[2], r[3]);
    }
}

// ---------------------------------------------------------------
extern "C" void kernel_launch(void* const* d_in, const int* in_sizes, int n_in,
                              void* d_out, int out_size)
{
    const float* src_pts = (const float*)d_in[0];
    const float* tgt_pts = (const float*)d_in[1];
    const float* cand    = (const float*)d_in[2];
    const float* W1      = (const float*)d_in[3];
    const float* b1      = (const float*)d_in[4];
    const float* W2      = (const float*)d_in[5];
    const float* b2      = (const float*)d_in[6];
    const float* Wq      = (const float*)d_in[7];
    const float* bq      = (const float*)d_in[8];
    float* out = (float*)d_out;

    feat_kernel<<<dim3(N_PTS / 128, 2), 128>>>(tgt_pts, src_pts, W1, b1, W2, b2, Wq, bq);
    topk_src_kernel<<<1, 128>>>(src_pts, out);
    ball_kernel<<<N_QUERY, 128>>>(cand, out);
}

// round 11
// speedup vs baseline: 1.7105x; 1.0706x over previous
#include <cuda_runtime.h>
#include <cstdint>

#define N_PTS    4096
#define N_QUERY  35328     // 64*552
#define NSAMPLE  32
#define FEAT_D   32
#define FEAT_H   64
#define OUT_BASE 384       // 64*6 src_keypts floats precede grouped output
#define ROW      35        // 3+FEAT_D
#define QROW     1120      // NSAMPLE*ROW
#define NBUCKET  256
#define CAND_CAP 64
#define NQ       4
#define NBLK     (N_QUERY / NQ)   // 8832 ball blocks; block NBLK = topk

// -------- scratch (static device globals: allocation-free) --------
__device__ float4 g_xyzp[N_PTS];             // tgt xyz + |p|^2
__device__ float  g_feat[N_PTS * FEAT_D];    // tgt feature rows [n][32]
__device__ float  g_scores[N_PTS];           // src softplus scores

// monotone float -> uint mapping (total order incl. negatives)
__device__ __forceinline__ unsigned int fmap(float f) {
    unsigned int u = __float_as_uint(f);
    return (u & 0x80000000u) ? ~u : (u | 0x80000000u);
}
__device__ __forceinline__ unsigned long long umin64(unsigned long long a, unsigned long long b) {
    return a < b ? a : b;
}
__device__ __forceinline__ unsigned long long umax64(unsigned long long a, unsigned long long b) {
    return a > b ? a : b;
}
__device__ __forceinline__ unsigned long long shfl_xor64(unsigned long long v, int m) {
    return __shfl_xor_sync(0xffffffffu, v, m);
}

// ---------------------------------------------------------------
// Kernel 1: feature MLP (fused src+tgt via blockIdx.y), 64-thread
// blocks for SM coverage. fp32 op order mirrors the XLA reference.
// ---------------------------------------------------------------
__global__ void __launch_bounds__(64) feat_kernel(
    const float* __restrict__ tgt_pts,
    const float* __restrict__ src_pts,
    const float* __restrict__ W1, const float* __restrict__ b1,
    const float* __restrict__ W2, const float* __restrict__ b2,
    const float* __restrict__ Wq, const float* __restrict__ bq)
{
    __shared__ float sW1[FEAT_H * 6], sb1[FEAT_H];
    __shared__ float sW2t[FEAT_H * FEAT_D];   // transposed: [k][o2]
    __shared__ float sb2[FEAT_D];
    __shared__ float sWq[FEAT_D], sbq;

    int tid  = threadIdx.x;
    int mode = blockIdx.y;           // 0 = tgt, 1 = src
    const float* pts = mode ? src_pts : tgt_pts;

    for (int i = tid; i < FEAT_H * 6; i += 64) sW1[i] = W1[i];
    for (int i = tid; i < FEAT_H;     i += 64) sb1[i] = b1[i];
    for (int i = tid; i < FEAT_D * FEAT_H; i += 64) {
        int o2 = i >> 6, k = i & 63;
        sW2t[k * FEAT_D + o2] = W2[i];
    }
    for (int i = tid; i < FEAT_D; i += 64) sb2[i] = b2[i];
    for (int i = tid; i < FEAT_D; i += 64) sWq[i] = Wq[i];
    if (tid == 0) sbq = bq[0];
    __syncthreads();

    int n = blockIdx.x * 64 + tid;

    float x[6];
#pragma unroll
    for (int c = 0; c < 6; c++) x[c] = pts[c * N_PTS + n];

    float facc[FEAT_D];
#pragma unroll 4
    for (int k = 0; k < FEAT_H; k++) {
        float acc = __fmul_rn(sW1[k * 6], x[0]);
#pragma unroll
        for (int c = 1; c < 6; c++) acc = __fmaf_rn(sW1[k * 6 + c], x[c], acc);
        float h = fmaxf(__fadd_rn(acc, sb1[k]), 0.0f);
        const float* w = &sW2t[k * FEAT_D];
        if (k == 0) {
#pragma unroll
            for (int o = 0; o < FEAT_D; o++) facc[o] = __fmul_rn(w[o], h);
        } else {
#pragma unroll
            for (int o = 0; o < FEAT_D; o++) facc[o] = __fmaf_rn(w[o], h, facc[o]);
        }
    }

    if (mode == 0) {
#pragma unroll
        for (int o = 0; o < FEAT_D; o++)
            g_feat[n * FEAT_D + o] = fmaxf(__fadd_rn(facc[o], sb2[o]), 0.0f);
        float pp = __fadd_rn(__fadd_rn(__fmul_rn(x[0], x[0]), __fmul_rn(x[1], x[1])),
                             __fmul_rn(x[2], x[2]));
        g_xyzp[n] = make_float4(x[0], x[1], x[2], pp);
    } else {
        float z = 0.0f;
#pragma unroll
        for (int o = 0; o < FEAT_D; o++) {
            float f = fmaxf(__fadd_rn(facc[o], sb2[o]), 0.0f);
            z = (o == 0) ? __fmul_rn(sWq[0], f) : __fmaf_rn(sWq[o], f, z);
        }
        z = __fadd_rn(z, sbq);
        // jax.nn.softplus = max(z,0) + log1p(exp(-|z|))
        g_scores[n] = __fadd_rn(fmaxf(z, 0.0f), log1pf(expf(-fabsf(z))));
    }
}

// ---------------------------------------------------------------
// Kernel 2: fused grid. Blocks [0, NBLK): ball query, NQ=4 queries
// per block, warp w owns query w's scan/sort. Block NBLK: src
// top-64 + keypts gather (smem union with the ball layout).
// ---------------------------------------------------------------
__global__ void __launch_bounds__(128) ball_kernel(
    const float* __restrict__ cand,
    const float* __restrict__ src_pts,
    float* __restrict__ out)
{
    __shared__ union {
        struct {
            unsigned int hist[NQ][NBUCKET];           // 4 KB
            unsigned long long scand[NQ][CAND_CAP];   // 2 KB
        } b;
        struct {
            float ss[N_PTS];                          // 16 KB
            unsigned long long schunk[128];           // 1 KB
        } t;
    } u;
    __shared__ unsigned long long sred[128];
    __shared__ int ssel[NQ][NSAMPLE];
    __shared__ int scut[NQ], scnt[NQ];

    const unsigned long long INVK = ~0ull;
    int tid  = threadIdx.x;
    int lane = tid & 31;
    int wid  = tid >> 5;

    // ================= topk block =================
    if (blockIdx.x == NBLK) {
        float* ss = u.t.ss;
        unsigned long long* schunk = u.t.schunk;
        int* sel = &ssel[0][0];                      // 128 ints available

        for (int i = tid; i < N_PTS; i += 128) ss[i] = g_scores[i];
        __syncthreads();
        {
            int c = tid;
            unsigned long long best = 0ull;
            for (int j = 0; j < 32; j++) {
                int i = (c << 5) + ((j + c) & 31);
                unsigned long long key = ((unsigned long long)fmap(ss[i]) << 32) |
                                         (unsigned long long)(0xFFFFFFFFu - (unsigned)i);
                best = umax64(best, key);
            }
            schunk[c] = best;
        }
        __syncthreads();
        if (tid < 32) {
            for (int k = 0; k < 64; k++) {
                unsigned long long b = 0ull;
#pragma unroll
                for (int j = 0; j < 4; j++) b = umax64(b, schunk[tid + 32 * j]);
#pragma unroll
                for (int off = 16; off; off >>= 1)
                    b = umax64(b, shfl_xor64(b, off));
                int w = (int)(0xFFFFFFFFu - (unsigned)(b & 0xFFFFFFFFull));
                int cidx = w >> 5;
                if (tid == 0) ss[w] = __int_as_float(0xFF800000);
                __syncwarp();
                int i2 = (cidx << 5) + tid;
                unsigned long long key2 = ((unsigned long long)fmap(ss[i2]) << 32) |
                                          (unsigned long long)(0xFFFFFFFFu - (unsigned)i2);
#pragma unroll
                for (int off = 16; off; off >>= 1)
                    key2 = umax64(key2, shfl_xor64(key2, off));
                if (tid == 0) { schunk[cidx] = key2; sel[k] = w; }
                __syncwarp();
            }
        }
        __syncthreads();
        for (int e = tid; e < 384; e += 128) {
            int kk = e / 6, c = e - kk * 6;
            out[e] = src_pts[c * N_PTS + sel[kk]];
        }
        return;
    }

    // ================= ball blocks =================
    int qid0 = blockIdx.x * NQ;

    unsigned int* hflat = &u.b.hist[0][0];
#pragma unroll
    for (int i = 0; i < NQ * NBUCKET / 128; i++) hflat[tid + i * 128] = 0u;
    if (tid < NQ) { scut[tid] = NBUCKET - 1; scnt[tid] = 0; }

    float qx[NQ], qy[NQ], qz[NQ], qw[NQ];
#pragma unroll
    for (int q = 0; q < NQ; q++) {
        qx[q] = __ldg(&cand[(qid0 + q) * 3 + 0]);
        qy[q] = __ldg(&cand[(qid0 + q) * 3 + 1]);
        qz[q] = __ldg(&cand[(qid0 + q) * 3 + 2]);
        qw[q] = __fadd_rn(__fadd_rn(__fmul_rn(qx[q], qx[q]), __fmul_rn(qy[q], qy[q])),
                          __fmul_rn(qz[q], qz[q]));
    }
    __syncthreads();

    // Pass 1: one point load -> NQ distances -> histograms
#pragma unroll 4
    for (int j = 0; j < 32; j++) {
        int p = j * 128 + tid;
        float4 P = g_xyzp[p];
#pragma unroll
        for (int q = 0; q < NQ; q++) {
            float E = __fmaf_rn(P.z, qz[q], __fmaf_rn(P.y, qy[q], __fmul_rn(P.x, qx[q])));
            float dd = __fadd_rn(__fsub_rn(qw[q], __fmul_rn(2.0f, E)), P.w);
            if (dd <= 4.0f) {
                int b = (int)(dd * 64.0f);
                b = b < 0 ? 0 : (b > NBUCKET - 1 ? NBUCKET - 1 : b);
                atomicAdd(&u.b.hist[q][b], 1u);
            }
        }
    }
    __syncthreads();

    // Per-warp scan: warp w locates query w's cut bucket (lane owns 8)
    {
        int base = lane * 8;
        int h[8];
        int psum = 0;
#pragma unroll
        for (int t = 0; t < 8; t++) { h[t] = u.b.hist[wid][base + t]; psum += h[t]; }
        int v = psum;
#pragma unroll
        for (int off = 1; off < 32; off <<= 1) {
            int uu = __shfl_up_sync(0xffffffffu, v, off);
            if (lane >= off) v += uu;
        }
        int total = __shfl_sync(0xffffffffu, v, 31);
        int excl = v - psum;
        if (total >= NSAMPLE && excl < NSAMPLE && v >= NSAMPLE) {
            int run = excl;
#pragma unroll
            for (int t = 0; t < 8; t++) {
                run += h[t];
                if (run >= NSAMPLE) { scut[wid] = base + t; break; }
            }
        }
    }
    __syncthreads();

    // Pass 2: recompute (bit-identical), collect bucket <= cut per query
#pragma unroll 4
    for (int j = 0; j < 32; j++) {
        int p = j * 128 + tid;
        float4 P = g_xyzp[p];
#pragma unroll
        for (int q = 0; q < NQ; q++) {
            float E = __fmaf_rn(P.z, qz[q], __fmaf_rn(P.y, qy[q], __fmul_rn(P.x, qx[q])));
            float dd = __fadd_rn(__fsub_rn(qw[q], __fmul_rn(2.0f, E)), P.w);
            if (dd <= 4.0f) {
                int b = (int)(dd * 64.0f);
                b = b < 0 ? 0 : (b > NBUCKET - 1 ? NBUCKET - 1 : b);
                if (b <= scut[q]) {
                    int pos = atomicAdd(&scnt[q], 1);
                    if (pos < CAND_CAP)
                        u.b.scand[q][pos] = ((unsigned long long)fmap(dd) << 32) |
                                            (unsigned long long)(unsigned)p;
                }
            }
        }
    }
    __syncthreads();

    // Per-warp 64-element bitonic sort: warp w sorts query w
    {
        int cnt = scnt[wid];
        if (cnt <= CAND_CAP) {
            unsigned long long a = (lane      < cnt) ? u.b.scand[wid][lane]      : INVK;
            unsigned long long b = (lane + 32 < cnt) ? u.b.scand[wid][lane + 32] : INVK;
            for (int k = 2; k <= 64; k <<= 1) {
                for (int j = k >> 1; j > 0; j >>= 1) {
                    if (j == 32) {
                        unsigned long long lo = umin64(a, b), hi = umax64(a, b);
                        a = lo; b = hi;
                    } else {
                        {
                            unsigned long long o = shfl_xor64(a, j);
                            bool asc = ((lane & k) == 0);
                            bool keepmin = (((lane & j) == 0) == asc);
                            a = keepmin ? umin64(a, o) : umax64(a, o);
                        }
                        {
                            unsigned long long o = shfl_xor64(b, j);
                            bool asc = (((lane + 32) & k) == 0);
                            bool keepmin = (((lane & j) == 0) == asc);
                            b = keepmin ? umin64(b, o) : umax64(b, o);
                        }
                    }
                }
            }
            unsigned long long a0 = __shfl_sync(0xffffffffu, a, 0);
            int myidx = (int)(unsigned)(a & 0xFFFFFFFFull);
            int idx0  = (int)(unsigned)(a0 & 0xFFFFFFFFull);
            bool av = (a != INVK), v0 = (a0 != INVK);
            ssel[wid][lane] = av ? myidx : (v0 ? idx0 : 0);
        }
    }
    __syncthreads();

    // Rare overflow fallback: block-wide exact extraction per query
    for (int q = 0; q < NQ; q++) {
        if (scnt[q] > CAND_CAP) {
            unsigned int removed = 0u;
            for (int k = 0; k < NSAMPLE; k++) {
                unsigned long long best = INVK;
                for (int j = 0; j < 32; j++) {
                    int p = j * 128 + tid;
                    float4 P = g_xyzp[p];
                    float E = __fmaf_rn(P.z, qz[q], __fmaf_rn(P.y, qy[q], __fmul_rn(P.x, qx[q])));
                    float dd = __fadd_rn(__fsub_rn(qw[q], __fmul_rn(2.0f, E)), P.w);
                    if (!((removed >> j) & 1u) && dd <= 4.0f)
                        best = umin64(best, ((unsigned long long)fmap(dd) << 32) |
                                            (unsigned long long)(unsigned)p);
                }
                sred[tid] = best;
                __syncthreads();
                for (int st = 64; st; st >>= 1) {
                    if (tid < st) sred[tid] = umin64(sred[tid], sred[tid + st]);
                    __syncthreads();
                }
                unsigned long long bb = sred[0];
                int w = (bb != INVK) ? (int)(unsigned)(bb & 0xFFFFFFFFull)
                                     : (k ? ssel[q][0] : 0);
                if ((w & 127) == tid && bb != INVK) removed |= 1u << (w >> 7);
                if (tid == 0) ssel[q][k] = w;
                __syncthreads();
            }
        }
    }
    __syncthreads();

    // Output: NQ x [NSAMPLE][3+FEAT_D], vectorized float4 stores
#pragma unroll
    for (int q = 0; q < NQ; q++) {
        float4* ob = (float4*)(out + OUT_BASE + (long long)(qid0 + q) * QROW);
        for (int v = tid; v < QROW / 4; v += 128) {
            int e = v * 4;
            int s = e / ROW;
            int c = e - s * ROW;
            float r[4];
#pragma unroll
            for (int t = 0; t < 4; t++) {
                int idx = ssel[q][s];
                float val;
                if (c < 3) {
                    const float* Pf = (const float*)&g_xyzp[idx];
                    float qc = (c == 0) ? qx[q] : ((c == 1) ? qy[q] : qz[q]);
                    val = __fsub_rn(Pf[c], qc);
                } else {
                    val = g_feat[idx * FEAT_D + (c - 3)];
                }
                r[t] = val;
                if (++c == ROW) { c = 0; ++s; }
            }
            ob[v] = make_float4(r[0], r[1], r[2], r[3]);
        }
    }
}

// ---------------------------------------------------------------
extern "C" void kernel_launch(void* const* d_in, const int* in_sizes, int n_in,
                              void* d_out, int out_size)
{
    const float* src_pts = (const float*)d_in[0];
    const float* tgt_pts = (const float*)d_in[1];
    const float* cand    = (const float*)d_in[2];
    const float* W1      = (const float*)d_in[3];
    const float* b1      = (const float*)d_in[4];
    const float* W2      = (const float*)d_in[5];
    const float* b2      = (const float*)d_in[6];
    const float* Wq      = (const float*)d_in[7];
    const float* bq      = (const float*)d_in[8];
    float* out = (float*)d_out;

    feat_kernel<<<dim3(N_PTS / 64, 2), 64>>>(tgt_pts, src_pts, W1, b1, W2, b2, Wq, bq);
    ball_kernel<<<NBLK + 1, 128>>>(cand, src_pts, out);
}